// round 3
// baseline (speedup 1.0000x reference)
#include <cuda_runtime.h>

// 16k -> 24k polyphase resampler (torchaudio/kaldi defaults).
// in_unit=2, out_unit=3 phases, first_indices={-6,-5,-4}, W=13 taps.
// out[c, n] = sum_j x[c, (n%3 - 6) + 2*(n/3) + j] * w[n%3][j], zero-padded x.
//
// Coalesced smem staging: block of 256 threads stages 2064 contiguous input
// floats (coalesced float4 LDG), stored with 4-float padding every 32 floats
// (stride-36 layout) so per-thread window reads (LDS.128, 8-float lane
// stride) are bank-conflict-free. Each thread computes 12 outputs.

#define C_CH    8
#define NPHASE  3
#define WTAPS   13
#define OUT_PT  12              // outputs per thread (4 units x 3 phases)
#define BLK     256
#define CHUNKS  516             // float4 chunks staged per block (2064 floats)
#define SPAD(c4) ((c4) + ((c4) >> 3))   // padded float4 slot index

__global__ __launch_bounds__(BLK, 3) void resample_16_24_kernel(
    const float* __restrict__ x, const float* __restrict__ wgt,
    float* __restrict__ out, int L, int tot)
{
    __shared__ float4 s[CHUNKS + (CHUNKS >> 3) + 2];   // ~9.3 KB padded

    const int tid = threadIdx.x;
    const int c   = blockIdx.y;
    const long long T0 = (long long)blockIdx.x * BLK;   // thread-tile base
    const long long G0 = 8 * T0 - 8;                    // first staged float

    const float* xc = x + (size_t)c * (size_t)L;

    // Filter bank into registers (uniform broadcast loads)
    float w[NPHASE][WTAPS];
#pragma unroll
    for (int i = 0; i < NPHASE; i++)
#pragma unroll
        for (int j = 0; j < WTAPS; j++)
            w[i][j] = __ldg(&wgt[i * WTAPS + j]);

    // ---- Stage input region [G0, G0+2064) into padded smem (coalesced) ----
#pragma unroll
    for (int m = 0; m < 3; m++) {
        int c4 = tid + BLK * m;
        if (c4 < CHUNKS) {
            long long g = G0 + 4LL * c4;
            float4 v;
            if (g >= 0 && g + 4 <= (long long)L) {
                v = *reinterpret_cast<const float4*>(xc + g);
            } else {
                float a[4];
#pragma unroll
                for (int q = 0; q < 4; q++) {
                    long long gg = g + q;
                    a[q] = (gg >= 0 && gg < (long long)L) ? xc[gg] : 0.0f;
                }
                v = make_float4(a[0], a[1], a[2], a[3]);
            }
            s[SPAD(c4)] = v;
        }
    }
    __syncthreads();

    // ---- Compute 12 outputs per thread ----
    const long long t  = T0 + tid;
    const long long n0 = t * OUT_PT;
    if (n0 >= tot) return;

    // Window: floats [8t-8, 8t+16) -> local float4 chunks c0 .. c0+5
    float xin[24];
    const int c0 = 2 * tid;
#pragma unroll
    for (int q = 0; q < 6; q++) {
        float4 v = s[SPAD(c0 + q)];
        xin[4*q+0] = v.x; xin[4*q+1] = v.y;
        xin[4*q+2] = v.z; xin[4*q+3] = v.w;
    }

    // n = n0 + 3u + i reads xin[(2+i+2u) .. +12]
    float o[OUT_PT];
#pragma unroll
    for (int u = 0; u < 4; u++) {
#pragma unroll
        for (int i = 0; i < NPHASE; i++) {
            const int base = 2 + i + 2 * u;
            float sacc = 0.0f;
#pragma unroll
            for (int j = 0; j < WTAPS; j++)
                sacc = fmaf(xin[base + j], w[i][j], sacc);
            o[3 * u + i] = sacc;
        }
    }

    float* oc = out + (size_t)c * (size_t)tot + n0;
    float4* po = reinterpret_cast<float4*>(oc);
    po[0] = make_float4(o[0], o[1], o[2],  o[3]);
    po[1] = make_float4(o[4], o[5], o[6],  o[7]);
    po[2] = make_float4(o[8], o[9], o[10], o[11]);
}

extern "C" void kernel_launch(void* const* d_in, const int* in_sizes, int n_in,
                              void* d_out, int out_size)
{
    const float* x   = (const float*)d_in[0];
    const float* wgt = (const float*)d_in[1];
    float* out = (float*)d_out;

    const int L   = in_sizes[0] / C_CH;   // 4,000,000
    const int tot = out_size   / C_CH;    // 6,000,000 (divisible by 12)

    const long long threads_per_ch = ((long long)tot + OUT_PT - 1) / OUT_PT;
    const int bx = (int)((threads_per_ch + BLK - 1) / BLK);
    dim3 grid(bx, C_CH);
    resample_16_24_kernel<<<grid, BLK>>>(x, wgt, out, L, tot);
}

// round 4
// speedup vs baseline: 1.5822x; 1.5822x over previous
#include <cuda_runtime.h>

// 16k -> 24k polyphase resampler (torchaudio/kaldi defaults).
// in_unit=2, out_unit=3 phases, first_indices={-6,-5,-4}, W=13 taps.
// out[c, n] = sum_j x[c, (n%3 - 6) + 2*(n/3) + j] * w[n%3][j], zero-padded x.
//
// R1 direct structure (best so far), with the 39-float filter bank moved to
// __constant__ memory (copied once per launch via async DtoD memcpy-to-symbol,
// graph-capturable). Weight reads leave the L1tex pipe (const/uniform port),
// freeing ~35% of L1 wavefronts and ~39 registers.

#define C_CH    8
#define NPHASE  3
#define WTAPS   13
#define OUT_PT  12   // outputs per thread (4 units x 3 phases)
#define BLK     256

__constant__ float cw[NPHASE * WTAPS];

__global__ __launch_bounds__(BLK) void resample_16_24_kernel(
    const float* __restrict__ x, float* __restrict__ out, int L, int tot)
{
    const int c = blockIdx.y;
    const int t = blockIdx.x * BLK + threadIdx.x;   // thread index in channel
    const int n0 = t * OUT_PT;
    if (n0 >= tot) return;

    const float* xc = x + (size_t)c * (size_t)L;

    // Input window: floats [8t-8, 8t+16), 16B aligned.
    const int g0 = 8 * t - 8;
    float xin[24];
    if (g0 >= 0 && g0 + 24 <= L) {
        const float4* p = reinterpret_cast<const float4*>(xc + g0);
#pragma unroll
        for (int q = 0; q < 6; q++) {
            float4 v = __ldg(&p[q]);
            xin[4*q+0] = v.x; xin[4*q+1] = v.y;
            xin[4*q+2] = v.z; xin[4*q+3] = v.w;
        }
    } else {
        // boundary threads (first/last per channel): guarded scalar loads
#pragma unroll
        for (int q = 0; q < 24; q++) {
            int g = g0 + q;
            xin[q] = (g >= 0 && g < L) ? xc[g] : 0.0f;
        }
    }

    // 12 outputs: n = n0 + 3u + i reads xin[(2+i+2u) .. +12], weights from
    // constant bank (literal offsets -> LDCU/UR operands, off the L1 path).
    float o[OUT_PT];
#pragma unroll
    for (int u = 0; u < 4; u++) {
#pragma unroll
        for (int i = 0; i < NPHASE; i++) {
            const int base = 2 + i + 2 * u;
            float s = 0.0f;
#pragma unroll
            for (int j = 0; j < WTAPS; j++)
                s = fmaf(xin[base + j], cw[i * WTAPS + j], s);
            o[3 * u + i] = s;
        }
    }

    float* oc = out + (size_t)c * (size_t)tot + n0;
    float4* po = reinterpret_cast<float4*>(oc);
    po[0] = make_float4(o[0], o[1], o[2],  o[3]);
    po[1] = make_float4(o[4], o[5], o[6],  o[7]);
    po[2] = make_float4(o[8], o[9], o[10], o[11]);
}

extern "C" void kernel_launch(void* const* d_in, const int* in_sizes, int n_in,
                              void* d_out, int out_size)
{
    const float* x   = (const float*)d_in[0];
    const float* wgt = (const float*)d_in[1];
    float* out = (float*)d_out;

    const int L   = in_sizes[0] / C_CH;   // 4,000,000
    const int tot = out_size   / C_CH;    // 6,000,000 (divisible by 12)

    // Stage filter bank into constant memory (DtoD, on captured legacy stream)
    cudaMemcpyToSymbolAsync(cw, wgt, NPHASE * WTAPS * sizeof(float), 0,
                            cudaMemcpyDeviceToDevice, 0);

    const int threads_per_ch = (tot + OUT_PT - 1) / OUT_PT;
    const int bx = (threads_per_ch + BLK - 1) / BLK;
    dim3 grid(bx, C_CH);
    resample_16_24_kernel<<<grid, BLK>>>(x, out, L, tot);
}

// round 5
// speedup vs baseline: 1.7437x; 1.1021x over previous
#include <cuda_runtime.h>

// 16k -> 24k polyphase resampler (torchaudio/kaldi defaults).
// in_unit=2, out_unit=3 phases, first_indices={-6,-5,-4}, W=13 taps.
// out[c, n] = sum_j x[c, (n%3 - 6) + 2*(n/3) + j] * w[n%3][j], zero-padded x.
//
// Warp-halo scheme: thread t owns input floats [8t, 8t+8) loaded as two
// coalesced LDG.128; the 8-float halos on each side come from lanes l-1/l+1
// via warp shuffle (off the L1tex pipe). Lanes 0/31 patch halos with
// predicated guarded loads. 12 outputs/thread, vector stores.

#define C_CH    8
#define NPHASE  3
#define WTAPS   13
#define OUT_PT  12   // outputs per thread (4 units x 3 phases)
#define BLK     256

__constant__ float cw[NPHASE * WTAPS];

__global__ __launch_bounds__(BLK, 6) void resample_16_24_kernel(
    const float* __restrict__ x, float* __restrict__ out, int L, int tot)
{
    const int c = blockIdx.y;
    const int t = blockIdx.x * BLK + threadIdx.x;
    const int n0 = t * OUT_PT;
    if (n0 >= tot) return;          // whole warps exit (500000 threads = 15625 full warps)

    const int lane = threadIdx.x & 31;
    const float* xc = x + (size_t)c * (size_t)L;
    const int g0 = 8 * t;           // own floats [g0, g0+8); g0+8 <= L always

    // Own data: 2 coalesced vector loads
    const float4* p = reinterpret_cast<const float4*>(xc + g0);
    float4 A = __ldg(&p[0]);
    float4 B = __ldg(&p[1]);

    // xin covers [8t-8, 8t+16)
    float xin[24];

    // Halos via shuffle (SHFL pipe, not L1)
    const unsigned m = 0xffffffffu;
    xin[0]  = __shfl_up_sync(m, A.x, 1);
    xin[1]  = __shfl_up_sync(m, A.y, 1);
    xin[2]  = __shfl_up_sync(m, A.z, 1);
    xin[3]  = __shfl_up_sync(m, A.w, 1);
    xin[4]  = __shfl_up_sync(m, B.x, 1);
    xin[5]  = __shfl_up_sync(m, B.y, 1);
    xin[6]  = __shfl_up_sync(m, B.z, 1);
    xin[7]  = __shfl_up_sync(m, B.w, 1);
    xin[8]  = A.x; xin[9]  = A.y; xin[10] = A.z; xin[11] = A.w;
    xin[12] = B.x; xin[13] = B.y; xin[14] = B.z; xin[15] = B.w;
    xin[16] = __shfl_down_sync(m, A.x, 1);
    xin[17] = __shfl_down_sync(m, A.y, 1);
    xin[18] = __shfl_down_sync(m, A.z, 1);
    xin[19] = __shfl_down_sync(m, A.w, 1);
    xin[20] = __shfl_down_sync(m, B.x, 1);
    xin[21] = __shfl_down_sync(m, B.y, 1);
    xin[22] = __shfl_down_sync(m, B.z, 1);
    xin[23] = __shfl_down_sync(m, B.w, 1);

    // Warp-edge lanes fetch their halo directly (rare guarded path only at
    // channel edges; otherwise two vector loads).
    if (lane == 0) {
        const int gl = g0 - 8;
        if (gl >= 0) {
            float4 PA = __ldg(&p[-2]);
            float4 PB = __ldg(&p[-1]);
            xin[0] = PA.x; xin[1] = PA.y; xin[2] = PA.z; xin[3] = PA.w;
            xin[4] = PB.x; xin[5] = PB.y; xin[6] = PB.z; xin[7] = PB.w;
        } else {
#pragma unroll
            for (int q = 0; q < 8; q++) {
                int g = gl + q;
                xin[q] = (g >= 0) ? xc[g] : 0.0f;
            }
        }
    }
    if (lane == 31) {
        const int gr = g0 + 8;
        if (gr + 8 <= L) {
            float4 NA = __ldg(&p[2]);
            float4 NB = __ldg(&p[3]);
            xin[16] = NA.x; xin[17] = NA.y; xin[18] = NA.z; xin[19] = NA.w;
            xin[20] = NB.x; xin[21] = NB.y; xin[22] = NB.z; xin[23] = NB.w;
        } else {
#pragma unroll
            for (int q = 0; q < 8; q++) {
                int g = gr + q;
                xin[16 + q] = (g < L) ? xc[g] : 0.0f;
            }
        }
    }

    // 12 outputs: n = n0 + 3u + i reads xin[(2+i+2u) .. +12]; weights from
    // constant bank. Compute quad-by-quad, store immediately (low liveness).
    float* oc = out + (size_t)c * (size_t)tot + n0;
    float4* po = reinterpret_cast<float4*>(oc);
#pragma unroll
    for (int q = 0; q < 3; q++) {
        float o4[4];
#pragma unroll
        for (int r = 0; r < 4; r++) {
            const int n = 4 * q + r;
            const int u = n / 3;
            const int i = n % 3;
            const int base = 2 + i + 2 * u;
            float s = 0.0f;
#pragma unroll
            for (int j = 0; j < WTAPS; j++)
                s = fmaf(xin[base + j], cw[i * WTAPS + j], s);
            o4[r] = s;
        }
        po[q] = make_float4(o4[0], o4[1], o4[2], o4[3]);
    }
}

extern "C" void kernel_launch(void* const* d_in, const int* in_sizes, int n_in,
                              void* d_out, int out_size)
{
    const float* x   = (const float*)d_in[0];
    const float* wgt = (const float*)d_in[1];
    float* out = (float*)d_out;

    const int L   = in_sizes[0] / C_CH;   // 4,000,000
    const int tot = out_size   / C_CH;    // 6,000,000 (divisible by 12)

    // Stage filter bank into constant memory (DtoD, on captured legacy stream)
    cudaMemcpyToSymbolAsync(cw, wgt, NPHASE * WTAPS * sizeof(float), 0,
                            cudaMemcpyDeviceToDevice, 0);

    const int threads_per_ch = (tot + OUT_PT - 1) / OUT_PT;
    const int bx = (threads_per_ch + BLK - 1) / BLK;
    dim3 grid(bx, C_CH);
    resample_16_24_kernel<<<grid, BLK>>>(x, out, L, tot);
}